// round 2
// baseline (speedup 1.0000x reference)
#include <cuda_runtime.h>
#include <math.h>

// Problem constants
#define BB 4
#define SS 2048
#define CC 768
#define HH 12
#define DD 64
#define C3 2304
#define BSROWS (BB * SS)          // 8192
#define HALF_D 32

// ---------------------------------------------------------------------------
// Scratch (device globals; no allocations allowed)
// ---------------------------------------------------------------------------
__device__ float g_qkv[(size_t)BSROWS * C3];            // 8192 x 2304
__device__ float g_q[(size_t)BB * HH * SS * DD];        // (B,H,S,D)
__device__ float g_k[(size_t)BB * HH * SS * DD];
__device__ float g_v[(size_t)BB * HH * SS * DD];
__device__ float g_y[(size_t)BSROWS * CC];              // (B,S,C) pre-proj
__device__ float g_cos[SS * HALF_D];
__device__ float g_sin[SS * HALF_D];

// ---------------------------------------------------------------------------
// RoPE tables (mirrors reference fp32 math)
// ---------------------------------------------------------------------------
__global__ void rope_tables_kernel() {
    int idx = blockIdx.x * blockDim.x + threadIdx.x;   // S*32 threads
    if (idx >= SS * HALF_D) return;
    int s = idx >> 5;
    int i = idx & 31;
    float theta = 1.0f / powf(10000.0f, (float)i * (1.0f / 32.0f));
    float f = (float)s * theta;
    g_cos[idx] = cosf(f);
    g_sin[idx] = sinf(f);
}

// ---------------------------------------------------------------------------
// Generic fp32 SGEMM tile routine: C[M,N] = A[M,K] * B[K,N], all row-major.
// 128x128 block tile, K-step 8, 8x8 per thread, 256 threads.
// Requires M%128==0, N%128==0, K%8==0.
// ---------------------------------------------------------------------------
__device__ __forceinline__ void sgemm_tile(
    const float* __restrict__ A, const float* __restrict__ Bm,
    float* __restrict__ Cm, int M, int N, int K)
{
    __shared__ float As[8][128];
    __shared__ float Bs[8][128];

    const int tid = threadIdx.x;
    const int m0 = blockIdx.y * 128;
    const int n0 = blockIdx.x * 128;

    const int arow = tid >> 1;            // 0..127
    const int acol = (tid & 1) * 4;       // 0 or 4
    const int brow = tid >> 5;            // 0..7
    const int bcol = (tid & 31) * 4;      // 0..124

    const int tx = tid & 15;              // 0..15
    const int ty = tid >> 4;              // 0..15

    float acc[8][8];
#pragma unroll
    for (int i = 0; i < 8; i++)
#pragma unroll
        for (int j = 0; j < 8; j++) acc[i][j] = 0.0f;

    const int ktiles = K >> 3;
    for (int kt = 0; kt < ktiles; kt++) {
        const int k0 = kt << 3;
        float4 av = *(const float4*)&A[(size_t)(m0 + arow) * K + k0 + acol];
        float4 bv = *(const float4*)&Bm[(size_t)(k0 + brow) * N + n0 + bcol];

        As[acol + 0][arow] = av.x;
        As[acol + 1][arow] = av.y;
        As[acol + 2][arow] = av.z;
        As[acol + 3][arow] = av.w;
        *(float4*)&Bs[brow][bcol] = bv;
        __syncthreads();

#pragma unroll
        for (int kk = 0; kk < 8; kk++) {
            float4 a0 = *(const float4*)&As[kk][ty * 8];
            float4 a1 = *(const float4*)&As[kk][ty * 8 + 4];
            float4 b0 = *(const float4*)&Bs[kk][tx * 8];
            float4 b1 = *(const float4*)&Bs[kk][tx * 8 + 4];
            float ar[8] = {a0.x, a0.y, a0.z, a0.w, a1.x, a1.y, a1.z, a1.w};
            float br[8] = {b0.x, b0.y, b0.z, b0.w, b1.x, b1.y, b1.z, b1.w};
#pragma unroll
            for (int i = 0; i < 8; i++)
#pragma unroll
                for (int j = 0; j < 8; j++)
                    acc[i][j] = fmaf(ar[i], br[j], acc[i][j]);
        }
        __syncthreads();
    }

#pragma unroll
    for (int i = 0; i < 8; i++) {
        float* crow = Cm + (size_t)(m0 + ty * 8 + i) * N + n0 + tx * 8;
        float4 c0 = {acc[i][0], acc[i][1], acc[i][2], acc[i][3]};
        float4 c1 = {acc[i][4], acc[i][5], acc[i][6], acc[i][7]};
        *(float4*)crow = c0;
        *(float4*)(crow + 4) = c1;
    }
}

// Specialized entry points so the host code never needs symbol addresses.
__global__ __launch_bounds__(256) void sgemm_qkv_kernel(
    const float* __restrict__ x, const float* __restrict__ Wqkv)
{
    sgemm_tile(x, Wqkv, g_qkv, BSROWS, C3, CC);
}

__global__ __launch_bounds__(256) void sgemm_proj_kernel(
    const float* __restrict__ Wproj, float* __restrict__ out)
{
    sgemm_tile(g_y, Wproj, out, BSROWS, CC, CC);
}

// ---------------------------------------------------------------------------
// RoPE + split + transpose: qkv (B,S,3C) -> q,k (roped), v in (B,H,S,D)
// ---------------------------------------------------------------------------
__global__ void rope_split_kernel() {
    int idx = blockIdx.x * blockDim.x + threadIdx.x;   // B*S*C threads
    const int total = BB * SS * CC;
    if (idx >= total) return;

    int c = idx % CC;
    int bs = idx / CC;
    int srow = bs % SS;
    int b = bs / SS;
    int h = c >> 6;
    int d = c & 63;

    const float* row = g_qkv + (size_t)bs * C3;
    float cosv = g_cos[srow * HALF_D + (d & 31)];
    float sinv = g_sin[srow * HALF_D + (d & 31)];

    float qv = row[c];
    float kv = row[CC + c];
    float vv = row[2 * CC + c];

    int other = (d < HALF_D) ? (c + HALF_D) : (c - HALF_D);
    float q_other = row[other];
    float k_other = row[CC + other];

    float qo, ko;
    if (d < HALF_D) {
        qo = qv * cosv - q_other * sinv;
        ko = kv * cosv - k_other * sinv;
    } else {
        qo = qv * cosv + q_other * sinv;
        ko = kv * cosv + k_other * sinv;
    }

    size_t outp = ((size_t)(b * HH + h) * SS + srow) * DD + d;
    g_q[outp] = qo;
    g_k[outp] = ko;
    g_v[outp] = vv;
}

// ---------------------------------------------------------------------------
// Flash attention, fp32. Block = 64 threads, each owns one query row.
// grid.x = S/64 (reversed so heavy diagonal blocks schedule first),
// grid.y = B*H.
// ---------------------------------------------------------------------------
__global__ __launch_bounds__(64) void attn_kernel() {
    const int qt = gridDim.x - 1 - blockIdx.x;     // query tile
    const int bh = blockIdx.y;
    const int b = bh / HH;
    const int h = bh % HH;
    const int tid = threadIdx.x;

    const size_t base = (size_t)bh * SS * DD;
    const int mrow = qt * 64 + tid;                // query seq position

    // log2(e) * D^-0.5 folded into Q
    const float sc = 0.125f * 1.4426950408889634f;

    float qr[64];
    {
        const float4* qp = (const float4*)(g_q + base + (size_t)mrow * DD);
#pragma unroll
        for (int i = 0; i < 16; i++) {
            float4 t4 = qp[i];
            qr[4 * i + 0] = t4.x * sc;
            qr[4 * i + 1] = t4.y * sc;
            qr[4 * i + 2] = t4.z * sc;
            qr[4 * i + 3] = t4.w * sc;
        }
    }

    float o[64];
#pragma unroll
    for (int i = 0; i < 64; i++) o[i] = 0.0f;
    float mi = -3.0e38f;
    float li = 0.0f;

    __shared__ float Ks[64 * 64];
    __shared__ float Vs[64 * 64];
    float4* kd = (float4*)Ks;
    float4* vd = (float4*)Vs;

    for (int t = 0; t <= qt; t++) {
        const float4* ksrc = (const float4*)(g_k + base + (size_t)t * 64 * DD);
        const float4* vsrc = (const float4*)(g_v + base + (size_t)t * 64 * DD);
        __syncthreads();
#pragma unroll
        for (int i = 0; i < 16; i++) {
            kd[i * 64 + tid] = ksrc[i * 64 + tid];
            vd[i * 64 + tid] = vsrc[i * 64 + tid];
        }
        __syncthreads();

        const bool diag = (t == qt);

        for (int jc = 0; jc < 64; jc += 8) {
            float s[8];
#pragma unroll
            for (int jj = 0; jj < 8; jj++) {
                const float4* kr = (const float4*)(Ks + (jc + jj) * 64);
                float a0 = 0.f, a1 = 0.f, a2 = 0.f, a3 = 0.f;
#pragma unroll
                for (int d4 = 0; d4 < 16; d4++) {
                    float4 kk = kr[d4];
                    a0 = fmaf(qr[4 * d4 + 0], kk.x, a0);
                    a1 = fmaf(qr[4 * d4 + 1], kk.y, a1);
                    a2 = fmaf(qr[4 * d4 + 2], kk.z, a2);
                    a3 = fmaf(qr[4 * d4 + 3], kk.w, a3);
                }
                s[jj] = (a0 + a1) + (a2 + a3);
                if (diag && (jc + jj) > tid) s[jj] = -3.0e38f;
            }

            float mnew = mi;
#pragma unroll
            for (int jj = 0; jj < 8; jj++) mnew = fmaxf(mnew, s[jj]);

            float cfac = exp2f(mi - mnew);
            mi = mnew;
            li *= cfac;
#pragma unroll
            for (int d = 0; d < 64; d++) o[d] *= cfac;

            float p[8];
#pragma unroll
            for (int jj = 0; jj < 8; jj++) {
                p[jj] = exp2f(s[jj] - mi);
                li += p[jj];
            }

#pragma unroll
            for (int jj = 0; jj < 8; jj++) {
                const float4* vr = (const float4*)(Vs + (jc + jj) * 64);
#pragma unroll
                for (int d4 = 0; d4 < 16; d4++) {
                    float4 vv = vr[d4];
                    o[4 * d4 + 0] = fmaf(p[jj], vv.x, o[4 * d4 + 0]);
                    o[4 * d4 + 1] = fmaf(p[jj], vv.y, o[4 * d4 + 1]);
                    o[4 * d4 + 2] = fmaf(p[jj], vv.z, o[4 * d4 + 2]);
                    o[4 * d4 + 3] = fmaf(p[jj], vv.w, o[4 * d4 + 3]);
                }
            }
        }
    }

    const float inv = 1.0f / li;
    float* yp = g_y + ((size_t)(b * SS + mrow)) * CC + h * DD;
#pragma unroll
    for (int i = 0; i < 16; i++) {
        float4 t4;
        t4.x = o[4 * i + 0] * inv;
        t4.y = o[4 * i + 1] * inv;
        t4.z = o[4 * i + 2] * inv;
        t4.w = o[4 * i + 3] * inv;
        *(float4*)(yp + 4 * i) = t4;
    }
}

// ---------------------------------------------------------------------------
// Launch — kernel launches ONLY, nothing else.
// ---------------------------------------------------------------------------
extern "C" void kernel_launch(void* const* d_in, const int* in_sizes, int n_in,
                              void* d_out, int out_size)
{
    const float* x     = (const float*)d_in[0];   // (B,S,C) = 8192x768
    const float* Wqkv  = (const float*)d_in[1];   // 768x2304
    const float* Wproj = (const float*)d_in[2];   // 768x768
    float* out = (float*)d_out;                   // (B,S,C)

    // 1. RoPE tables
    rope_tables_kernel<<<(SS * HALF_D + 255) / 256, 256>>>();

    // 2. QKV GEMM: (8192x768) @ (768x2304)
    {
        dim3 grid(C3 / 128, BSROWS / 128);
        sgemm_qkv_kernel<<<grid, 256>>>(x, Wqkv);
    }

    // 3. RoPE + split + transpose
    {
        int total = BB * SS * CC;
        rope_split_kernel<<<(total + 255) / 256, 256>>>();
    }

    // 4. Flash attention
    {
        dim3 grid(SS / 64, BB * HH);
        attn_kernel<<<grid, 64>>>();
    }

    // 5. Output projection: (8192x768) @ (768x768)
    {
        dim3 grid(CC / 128, BSROWS / 128);
        sgemm_proj_kernel<<<grid, 256>>>(Wproj, out);
    }
}